// round 16
// baseline (speedup 1.0000x reference)
#include <cuda_runtime.h>

// FilterbankAttention v4: LDG-count reduction.
// Stage1: X via single LDG.128 quad per warp-row (ulonglong2 -> two f32x2 pairs,
// no packing), FY as float table in static smem (broadcast LDS.128 + dup movs).
// T2 quad mapping: pair(4L,4L+1)->row L, pair(4L+2,4L+3)->row L+32 (keeps the
// conflict-free stride-65 bank pattern). Stage2: physical-row remap, FX ull-pair
// table in global (uniform LDG.128), paired accumulation + final hadd.

#define NTHREADS 512
#define NTH_SETUP 1024
typedef unsigned long long ull;

__device__ __align__(16) float d_FYf[2048];  // [g16][j32][ni4] float, gamma/SY folded
__device__ __align__(16) ull d_FXp[1024];    // [g16][jp16][ni4] (f_c0, f_c0+1), 1/SX folded
__device__ int d_gsY[16];
__device__ int d_gsX2[16];   // even window start / 2
__device__ int d_Wr;

static __device__ __forceinline__ void upk2(ull v, float &a, float &b) {
    asm("mov.b64 {%0,%1}, %2;" : "=f"(a), "=f"(b) : "l"(v));
}
static __device__ __forceinline__ ull dup2(float a) {
    ull r;
    asm("mov.b64 %0, {%1,%1};" : "=l"(r) : "f"(a));
    return r;
}
static __device__ __forceinline__ void ffma2(ull &d, ull a, ull b) {
    asm("fma.rn.f32x2 %0, %1, %2, %0;" : "+l"(d) : "l"(a), "l"(b));
}
static __device__ __forceinline__ float hadd(ull v) {
    float a, b; upk2(v, a, b); return a + b;
}

// ---------------------------------------------------------------------------
// Setup: one block, 1024 threads.
// ---------------------------------------------------------------------------
__global__ void __launch_bounds__(NTH_SETUP)
fb_setup_kernel(const float *__restrict__ h, const float *__restrict__ Ww,
                const float *__restrict__ Wb) {
    __shared__ float sp[5];
    __shared__ float sc[8];   // 0:inv2v 1:d 2:gY 3:gX 4:gamma/SY 5:1/SX 6:gamma
    __shared__ int   sgsY[16], sgsX[16], sWr;
    __shared__ float ry[32], rx[32];

    const int tid = threadIdx.x, wid = tid >> 5, lane = tid & 31;

    if (wid < 5) {                                   // params = h[0] @ W^T + b
        float s = 0.0f;
        for (int k = lane; k < 512; k += 32) s += h[k] * Ww[wid * 512 + k];
        #pragma unroll
        for (int o = 16; o; o >>= 1) s += __shfl_down_sync(0xffffffffu, s, o);
        if (lane == 0) sp[wid] = s + Wb[wid];
    }
    __syncthreads();

    if (tid == 0) {
        float var   = expf(sp[2] + 1e-8f);
        float dd    = expf(sp[3]) * (127.0f / 63.0f);
        float gX    = 129.0f * (sp[0] + 1.0f) * 0.5f;
        float gY    = 129.0f * (sp[1] + 1.0f) * 0.5f;
        float gamma = expf(sp[4]);
        float inv2v = 0.5f / var;
        float r    = sqrtf(34.5f * var);             // exp(-r^2/2var) ~ 3e-8
        float half = r + 1.5f * dd + 2.0f;           // group span + even-align margin
        int Wr = (int)ceilf(2.0f * half);
        Wr = (Wr + 3) & ~3;
        if (Wr < 8)  Wr = 8;
        if (Wr > 32) Wr = 32;
        sWr = Wr;
        sc[0] = inv2v; sc[1] = dd; sc[2] = gY; sc[3] = gX; sc[6] = gamma;
        for (int g = 0; g < 16; g++) {
            float cY = gY + ((float)(4 * g) - 31.0f) * dd;
            int s = __float2int_rn(cY) - Wr / 2;
            sgsY[g] = max(0, min(128 - Wr, s));
            float cX = gX + ((float)(4 * g) - 31.0f) * dd;
            int sx = (__float2int_rn(cX) - Wr / 2) & ~1;   // even for pairing
            sgsX[g] = max(0, min(128 - Wr, sx));
        }
    }
    __syncthreads();

    const float inv2v = sc[0], dd = sc[1], gY = sc[2], gX = sc[3];

    float sy = 0.0f, sx = 0.0f;        // exact global sums, full 64x128 banks
    for (int i = tid; i < 8192; i += NTH_SETUP) {
        int n = i >> 7, a = i & 127;
        float muY = gY + ((float)n - 32.5f) * dd;
        float muX = gX + ((float)n - 32.5f) * dd;
        float dy = (float)a - muY, dx = (float)a - muX;
        sy += expf(-dy * dy * inv2v);
        sx += expf(-dx * dx * inv2v);
    }
    #pragma unroll
    for (int o = 16; o; o >>= 1) {
        sy += __shfl_down_sync(0xffffffffu, sy, o);
        sx += __shfl_down_sync(0xffffffffu, sx, o);
    }
    if (lane == 0) { ry[wid] = sy; rx[wid] = sx; }
    __syncthreads();
    if (tid == 0) {
        float SY = 0.0f, SX = 0.0f;
        for (int w = 0; w < NTH_SETUP / 32; w++) { SY += ry[w]; SX += rx[w]; }
        sc[4] = sc[6] / SY;
        sc[5] = 1.0f / SX;
    }
    __syncthreads();

    const float fyS = sc[4], fxS = sc[5];
    const int Wr = sWr;

    // FY float table [g][j][ni]
    for (int i = tid; i < 2048; i += NTH_SETUP) {
        int g = i >> 7, rem = i & 127, j = rem >> 2, ni = rem & 3;
        int n = 4 * g + ni;
        float vy = 0.0f;
        if (j < Wr) {
            float muY = gY + ((float)n - 32.5f) * dd;
            float dy = (float)(sgsY[g] + j) - muY;
            vy = expf(-dy * dy * inv2v) * fyS;
        }
        d_FYf[i] = vy;
    }
    // FX adjacent-pair table [g][jp][ni]
    for (int i = tid; i < 1024; i += NTH_SETUP) {
        int g = i >> 6, rem = i & 63, jp = rem >> 2, ni = rem & 3;
        int n = 4 * g + ni;
        float muX = gX + ((float)n - 32.5f) * dd;
        float v0 = 0.0f, v1 = 0.0f;
        int c0 = sgsX[g] + 2 * jp;
        if (2 * jp < Wr) {
            float dx0 = (float)c0 - muX;
            float dx1 = (float)(c0 + 1) - muX;
            v0 = expf(-dx0 * dx0 * inv2v) * fxS;
            v1 = expf(-dx1 * dx1 * inv2v) * fxS;
        }
        d_FXp[i] = (ull)__float_as_uint(v0) | ((ull)__float_as_uint(v1) << 32);
    }
    if (tid < 16) { d_gsY[tid] = sgsY[tid]; d_gsX2[tid] = sgsX[tid] >> 1; }
    if (tid == 0) d_Wr = sWr;
}

// ---------------------------------------------------------------------------
// Main: one CTA per (image, src) task. grid.x = 2*batch.
// T2 physical rows: row r<32 holds c-pair (4r, 4r+1); row r>=32 holds
// (4(r-32)+2, 4(r-32)+3). Both per-n entries of a column pair stay adjacent.
// ---------------------------------------------------------------------------
__global__ void __launch_bounds__(NTHREADS)
fb_main_kernel(const float *__restrict__ x, const float *__restrict__ xh,
               float *__restrict__ out) {
    __shared__ ull   T2[64 * 65];      // 33280 B
    __shared__ float FYs[2048];        // 8192 B

    const int tid = threadIdx.x, wid = tid >> 5, lane = tid & 31;
    const int t = blockIdx.x;
    const int Wr = d_Wr;

    // copy FY table to smem (one float4 per thread)
    reinterpret_cast<float4 *>(FYs)[tid] =
        reinterpret_cast<const float4 *>(d_FYf)[tid];
    __syncthreads();

    const float *Xg = ((t & 1) ? xh : x) + (size_t)(t >> 1) * 16384;

    // stage 1: quad of columns per lane, one LDG.128 per row per warp
    {
        const int aB = d_gsY[wid];
        const float4 *Fq = reinterpret_cast<const float4 *>(FYs) + wid * 32;
        ull acc[4][2];
        #pragma unroll
        for (int i = 0; i < 4; i++) { acc[i][0] = 0ull; acc[i][1] = 0ull; }
        const ulonglong2 *Xq =
            reinterpret_cast<const ulonglong2 *>(Xg) + (size_t)aB * 32 + lane;
        #pragma unroll 2
        for (int j = 0; j < Wr; j++) {
            ulonglong2 xq = __ldg(Xq);     // c = 4L..4L+3 : pairs (x01, x23)
            Xq += 32;
            float4 f = Fq[j];              // broadcast LDS.128
            ull f0 = dup2(f.x), f1 = dup2(f.y), f2 = dup2(f.z), f3 = dup2(f.w);
            ffma2(acc[0][0], xq.x, f0); ffma2(acc[0][1], xq.y, f0);
            ffma2(acc[1][0], xq.x, f1); ffma2(acc[1][1], xq.y, f1);
            ffma2(acc[2][0], xq.x, f2); ffma2(acc[2][1], xq.y, f2);
            ffma2(acc[3][0], xq.x, f3); ffma2(acc[3][1], xq.y, f3);
        }
        #pragma unroll
        for (int ni = 0; ni < 4; ni++) {
            const int n = 4 * wid + ni;
            T2[lane * 65 + n]        = acc[ni][0];   // pair (4L,   4L+1)
            T2[(lane + 32) * 65 + n] = acc[ni][1];   // pair (4L+2, 4L+3)
        }
    }
    __syncthreads();

    // stage 2: out[n][m] = sum over column pairs; physical-row remap
    {
        const int gm = wid;
        const int cB2 = d_gsX2[gm];
        const ulonglong2 *Fp =
            reinterpret_cast<const ulonglong2 *>(d_FXp) + gm * 32;
        ull accA[4] = {0ull, 0ull, 0ull, 0ull};   // n = lane
        ull accB[4] = {0ull, 0ull, 0ull, 0ull};   // n = lane+32
        const int half = Wr >> 1;
        #pragma unroll 2
        for (int jp = 0; jp < half; jp++) {
            const int q = cB2 + jp;                  // column pair index c0/2
            const int r = (q >> 1) + ((q & 1) << 5); // physical T2 row
            const ull *tr = T2 + r * 65;
            ull tA = tr[lane];
            ull tB = tr[lane + 32];
            ulonglong2 f01 = __ldg(Fp + 2 * jp);
            ulonglong2 f23 = __ldg(Fp + 2 * jp + 1);
            ffma2(accA[0], tA, f01.x); ffma2(accB[0], tB, f01.x);
            ffma2(accA[1], tA, f01.y); ffma2(accB[1], tB, f01.y);
            ffma2(accA[2], tA, f23.x); ffma2(accB[2], tB, f23.x);
            ffma2(accA[3], tA, f23.y); ffma2(accB[3], tB, f23.y);
        }
        float *ob = out + (size_t)(t >> 1) * 8192 + (size_t)(t & 1) * 4096 + gm * 4;
        *reinterpret_cast<float4 *>(ob + (size_t)lane * 64) =
            make_float4(hadd(accA[0]), hadd(accA[1]), hadd(accA[2]), hadd(accA[3]));
        *reinterpret_cast<float4 *>(ob + (size_t)(lane + 32) * 64) =
            make_float4(hadd(accB[0]), hadd(accB[1]), hadd(accB[2]), hadd(accB[3]));
    }
}

extern "C" void kernel_launch(void* const* d_in, const int* in_sizes, int n_in,
                              void* d_out, int out_size) {
    const float *x  = (const float *)d_in[0];
    const float *xh = (const float *)d_in[1];
    const float *h  = (const float *)d_in[2];
    const float *Ww = (const float *)d_in[3];
    const float *Wb = (const float *)d_in[4];
    float *out = (float *)d_out;

    const int batch   = in_sizes[0] / 16384;
    const int n_tasks = 2 * batch;

    fb_setup_kernel<<<1, NTH_SETUP>>>(h, Ww, Wb);
    fb_main_kernel<<<n_tasks, NTHREADS>>>(x, xh, out);
}